// round 15
// baseline (speedup 1.0000x reference)
#include <cuda_runtime.h>

#define TB      16
#define THREADS 384
#define LDIN    52      // s_in row stride (48 k-slots + 4 pad)
#define LDA     132     // activation row stride (128 + 4 pad)

// smem float offsets
#define SM_IN    0
#define SM_OEMB  (3*TB*LDIN)
#define SM_OA    (SM_OEMB + 3*TB*LDA)
#define SM_K     (SM_OA   + 3*TB*LDA)
#define SM_V     (SM_K    + 3*TB*LDA)
#define SMEM_FLOATS (SM_V + 3*TB*LDA)   // 27840 floats = 108.75 KB

// weight-fragment scratch (uint4 units). Section bases in uint4:
#define F_WO   0
#define F_WOA  4608
#define F_WQ   9216
#define F_WK   13312
#define F_WV   17408
#define F_WC1  21504
#define F_WC2  46080
#define F_TOTAL 47616        // 190464 floats
__device__ uint4 g_fragv[F_TOTAL];

__device__ __forceinline__ unsigned tf32r(float x) {
    unsigned u; asm("cvt.rna.tf32.f32 %0, %1;" : "=r"(u) : "f"(x)); return u;
}

// ---------------- prep: weights -> tf32 B-fragments ----------------
// layout per matrix/agent: [nt][kp][lane][r];  k = kp*16+(r>>1)*8+(r&1)*4+(lane&3),
// n = nt*8 + (lane>>2)
__global__ void prep_kernel(const float* __restrict__ W_o,  const float* __restrict__ W_oa,
                            const float* __restrict__ Wq,   const float* __restrict__ Wk,
                            const float* __restrict__ Wv,   const float* __restrict__ Wc1,
                            const float* __restrict__ Wc2)
{
    int idx = blockIdx.x * 256 + threadIdx.x;
    if (idx >= 190464) return;
    float v;
    if (idx < 184320) {
        const float* src; int base, kptot, kvalid, astride;
        if      (idx < 18432) { src = W_o;  base = 0;     kptot = 3;  kvalid = 30;  astride = 30*128;  }
        else if (idx < 36864) { src = W_oa; base = 18432; kptot = 3;  kvalid = 39;  astride = 39*128;  }
        else if (idx < 53248) { src = Wq;   base = 36864; kptot = 8;  kvalid = 128; astride = 0;       }
        else if (idx < 69632) { src = Wk;   base = 53248; kptot = 8;  kvalid = 128; astride = 0;       }
        else if (idx < 86016) { src = Wv;   base = 69632; kptot = 8;  kvalid = 128; astride = 0;       }
        else                  { src = Wc1;  base = 86016; kptot = 16; kvalid = 256; astride = 256*128; }
        int m   = idx - base;
        int per = 16 * kptot * 128;
        int ag  = m / per;  m -= ag * per;
        int nt  = m / (kptot * 128);
        int m2  = m - nt * (kptot * 128);
        int kp  = m2 >> 7, li = m2 & 127;
        int lane = li >> 2, rr = li & 3;
        int k = kp*16 + (rr>>1)*8 + (rr&1)*4 + (lane&3);
        int n = nt*8 + (lane>>2);
        v = (k < kvalid) ? src[(size_t)ag*astride + k*128 + n] : 0.f;
    } else {
        // Wc2: [3][128][9], N padded to 16. [ag][nt(2)][kp(8)][lane][r]
        int m  = idx - 184320;
        int ag = m / 2048; m -= ag * 2048;
        int nt = m >> 10;  m &= 1023;
        int kp = m >> 7;
        int li = m & 127;
        int lane = li >> 2, rr = li & 3;
        int k = kp*16 + (rr>>1)*8 + (rr&1)*4 + (lane&3);
        int n = nt*8 + (lane>>2);
        v = (n < 9) ? Wc2[ag*1152 + k*9 + n] : 0.f;
    }
    ((unsigned*)g_fragv)[idx] = tf32r(v);
}

// ---------------- warp-level tensor GEMM primitives (M=16) ----------------
__device__ __forceinline__ void mma8(float* d, const unsigned* a, unsigned b0, unsigned b1) {
    asm volatile("mma.sync.aligned.m16n8k8.row.col.f32.tf32.tf32.f32 "
                 "{%0,%1,%2,%3}, {%4,%5,%6,%7}, {%8,%9}, {%0,%1,%2,%3};"
                 : "+f"(d[0]), "+f"(d[1]), "+f"(d[2]), "+f"(d[3])
                 : "r"(a[0]), "r"(a[1]), "r"(a[2]), "r"(a[3]), "r"(b0), "r"(b1));
}

// M=16 A-fragments: a[tt][r] ; 8 conflict-free LDS.32 per kp
#define LOAD_AFRAG(a, Abase, lda, kp) { \
    _Pragma("unroll") \
    for (int tt = 0; tt < 2; tt++) { \
        const float* p = (Abase) + ra*(lda) + (kp)*16 + tt*8 + ca; \
        a[tt][0] = __float_as_uint(p[0]); \
        a[tt][1] = __float_as_uint(p[8*(lda)]); \
        a[tt][2] = __float_as_uint(p[4]); \
        a[tt][3] = __float_as_uint(p[8*(lda) + 4]); \
    } }

template<int KPC, int KPT>
__device__ __forceinline__ void warp_gemm(const float* __restrict__ Abase, int lda,
                                          const uint4* __restrict__ frag,
                                          int lane, float (*d)[4])
{
    const int ra = lane >> 2, ca = lane & 3;
    #pragma unroll 2
    for (int kp = 0; kp < KPC; kp++) {
        unsigned a[2][4];
        LOAD_AFRAG(a, Abase, lda, kp);
        #pragma unroll
        for (int nt = 0; nt < 4; nt++) {
            uint4 b = frag[(nt*KPT + kp)*32 + lane];
            mma8(d[nt], a[0], b.x, b.y);
            mma8(d[nt], a[1], b.z, b.w);
        }
    }
}

// two GEMMs sharing the same A fragments (halves A-LDS traffic)
template<int KPC, int KPT>
__device__ __forceinline__ void warp_gemm_dual(const float* __restrict__ Abase, int lda,
                                               const uint4* __restrict__ f1,
                                               const uint4* __restrict__ f2,
                                               int lane, float (*d1)[4], float (*d2)[4])
{
    const int ra = lane >> 2, ca = lane & 3;
    #pragma unroll 2
    for (int kp = 0; kp < KPC; kp++) {
        unsigned a[2][4];
        LOAD_AFRAG(a, Abase, lda, kp);
        #pragma unroll
        for (int nt = 0; nt < 4; nt++) {
            uint4 b = f1[(nt*KPT + kp)*32 + lane];
            mma8(d1[nt], a[0], b.x, b.y);
            mma8(d1[nt], a[1], b.z, b.w);
            uint4 c = f2[(nt*KPT + kp)*32 + lane];
            mma8(d2[nt], a[0], c.x, c.y);
            mma8(d2[nt], a[1], c.z, c.w);
        }
    }
}

#define K_PLAIN 0
#define K_LKYRND 1

__device__ __forceinline__ void store_d(float (*d)[4], float* __restrict__ dst, int ldd,
                                        const float* __restrict__ bias, int colBase,
                                        int lane, int kind)
{
    const int rr = lane >> 2, cc = (lane & 3) * 2;
    #pragma unroll
    for (int nt = 0; nt < 4; nt++) {
        int col = colBase + nt*8 + cc;
        float2 b2 = *(const float2*)(bias + col);
        float v0 = d[nt][0] + b2.x, v1 = d[nt][1] + b2.y;
        float v2 = d[nt][2] + b2.x, v3 = d[nt][3] + b2.y;
        if (kind == K_LKYRND) {
            v0 = (v0 >= 0.f) ? v0 : 0.01f*v0;  v1 = (v1 >= 0.f) ? v1 : 0.01f*v1;
            v2 = (v2 >= 0.f) ? v2 : 0.01f*v2;  v3 = (v3 >= 0.f) ? v3 : 0.01f*v3;
            v0 = __uint_as_float(tf32r(v0)); v1 = __uint_as_float(tf32r(v1));
            v2 = __uint_as_float(tf32r(v2)); v3 = __uint_as_float(tf32r(v3));
        }
        *(float2*)&dst[rr*ldd + col]       = make_float2(v0, v1);
        *(float2*)&dst[(rr + 8)*ldd + col] = make_float2(v2, v3);
    }
}

__device__ __forceinline__ void zero_d(float (*d)[4]) {
    #pragma unroll
    for (int nt = 0; nt < 4; nt++)
        #pragma unroll
        for (int i = 0; i < 4; i++) d[nt][i] = 0.f;
}

__global__ __launch_bounds__(THREADS, 2)
void valuenet_kernel(
    const float* __restrict__ obs,  const float* __restrict__ act,
    const float* __restrict__ b_o,  const float* __restrict__ b_oa,
    const float* __restrict__ bq,   const float* __restrict__ bk,
    const float* __restrict__ bv,   const float* __restrict__ bc1,
    const float* __restrict__ bc2,  float* __restrict__ out)
{
    extern __shared__ float sm[];
    float* s_in   = sm + SM_IN;     // inputs; later P5 partial scratch
    float* s_oemb = sm + SM_OEMB;
    float* s_oa   = sm + SM_OA;     // oa_emb -> Q -> attn_out
    float* s_K    = sm + SM_K;      // K, later h1
    float* s_V    = sm + SM_V;

    const int t    = threadIdx.x;
    const int w    = t >> 5, lane = t & 31;
    const int ag   = w >> 2, wn = w & 3;     // agent, N-warp
    const int e0g  = blockIdx.x * TB;

    // ---------------- P0: stage inputs (tf32-rounded) ----------------
    for (int i = t; i < TB * 90; i += THREADS) {
        int e = i / 90, rr = i - e * 90;
        int nn = rr / 30, dd = rr - nn * 30;
        s_in[(nn * TB + e) * LDIN + dd] =
            __uint_as_float(tf32r(obs[(long)(e0g + e) * 90 + rr]));
    }
    for (int i = t; i < TB * 27; i += THREADS) {
        int e = i / 27, rr = i - e * 27;
        int nn = rr / 9, dd = 30 + (rr - nn * 9);
        s_in[(nn * TB + e) * LDIN + dd] =
            __uint_as_float(tf32r(act[(long)(e0g + e) * 27 + rr]));
    }
    for (int i = t; i < 3 * TB * 9; i += THREADS) {  // zero k-slots 39..47
        int row = i / 9, kk = 39 + (i - (i/9)*9);
        s_in[row * LDIN + kk] = 0.f;
    }
    __syncthreads();

    // ---------------- P1: per-agent embeds (dual tensor, shared A) ----------------
    {
        float d1[4][4], d2[4][4];
        zero_d(d1); zero_d(d2);
        warp_gemm_dual<3,3>(s_in + ag*TB*LDIN, LDIN,
                            g_fragv + F_WO  + ag*1536 + wn*384,
                            g_fragv + F_WOA + ag*1536 + wn*384, lane, d1, d2);
        store_d(d1, s_oemb + ag*TB*LDA, LDA, b_o + ag*128, wn*32, lane, K_LKYRND);
        store_d(d2, s_oa   + ag*TB*LDA, LDA, b_oa + ag*128, wn*32, lane, K_LKYRND);
    }
    __syncthreads();

    // ---------------- P2a: K and V (dual tensor, shared A = oa_emb) ----------------
    {
        float d1[4][4], d2[4][4];
        zero_d(d1); zero_d(d2);
        warp_gemm_dual<8,8>(s_oa + ag*TB*LDA, LDA,
                            g_fragv + F_WK + wn*1024,
                            g_fragv + F_WV + wn*1024, lane, d1, d2);
        store_d(d1, s_K + ag*TB*LDA, LDA, bk, wn*32, lane, K_PLAIN);
        store_d(d2, s_V + ag*TB*LDA, LDA, bv, wn*32, lane, K_PLAIN);
    }
    __syncthreads();

    // ---------------- P2b: Q (oa region becomes Q) ----------------
    {
        float d[4][4];
        zero_d(d);
        warp_gemm<8,8>(s_oemb + ag*TB*LDA, LDA, g_fragv + F_WQ + wn*1024, lane, d);
        store_d(d, s_oa + ag*TB*LDA, LDA, bq, wn*32, lane, K_PLAIN);
    }
    __syncthreads();

    // ---------------- P3: 3-agent masked attention (scalar fp32) ----------------
    {
        const int n  = t >> 7;
        const int r  = t & 127;
        const int hg = r & 31, eg = r >> 5;
        const int h0 = hg * 4, eb = eg * 4;
        const float scale = 0.17677669529663689f;  // 1/sqrt(32)
        #pragma unroll
        for (int ei = 0; ei < 4; ei++) {
            const int e = eb + ei;
            float4 q  = *(float4*)&s_oa[(n*TB + e)*LDA + h0];
            float4 k0 = *(float4*)&s_K[(0*TB + e)*LDA + h0];
            float4 k1 = *(float4*)&s_K[(1*TB + e)*LDA + h0];
            float4 k2 = *(float4*)&s_K[(2*TB + e)*LDA + h0];
            float s0 = q.x*k0.x + q.y*k0.y + q.z*k0.z + q.w*k0.w;
            float s1 = q.x*k1.x + q.y*k1.y + q.z*k1.z + q.w*k1.w;
            float s2 = q.x*k2.x + q.y*k2.y + q.z*k2.z + q.w*k2.w;
            #pragma unroll
            for (int off = 4; off > 0; off >>= 1) {
                s0 += __shfl_xor_sync(0xffffffffu, s0, off);
                s1 += __shfl_xor_sync(0xffffffffu, s1, off);
                s2 += __shfl_xor_sync(0xffffffffu, s2, off);
            }
            s0 *= scale; s1 *= scale; s2 *= scale;
            if (n == 0)      s0 -= 1e10f;
            else if (n == 1) s1 -= 1e10f;
            else             s2 -= 1e10f;
            float mx  = fmaxf(s0, fmaxf(s1, s2));
            float p0  = __expf(s0 - mx);
            float p1  = __expf(s1 - mx);
            float p2  = __expf(s2 - mx);
            float inv = 1.0f / (p0 + p1 + p2);
            p0 *= inv; p1 *= inv; p2 *= inv;
            float4 v0 = *(float4*)&s_V[(0*TB + e)*LDA + h0];
            float4 v1 = *(float4*)&s_V[(1*TB + e)*LDA + h0];
            float4 v2 = *(float4*)&s_V[(2*TB + e)*LDA + h0];
            float4 ao;
            ao.x = __uint_as_float(tf32r(p0*v0.x + p1*v1.x + p2*v2.x));
            ao.y = __uint_as_float(tf32r(p0*v0.y + p1*v1.y + p2*v2.y));
            ao.z = __uint_as_float(tf32r(p0*v0.z + p1*v1.z + p2*v2.z));
            ao.w = __uint_as_float(tf32r(p0*v0.w + p1*v1.w + p2*v2.w));
            *(float4*)&s_oa[(n*TB + e)*LDA + h0] = ao;   // attn_out
        }
    }
    __syncthreads();

    // ---------------- P4: critic layer 1 (tensor, 256 -> 128) ----------------
    {
        float d[4][4];
        zero_d(d);
        const uint4* fc = g_fragv + F_WC1 + ag*8192 + wn*2048;   // KPT=16
        warp_gemm<8,16>(s_oemb + ag*TB*LDA, LDA, fc, lane, d);
        warp_gemm<8,16>(s_oa   + ag*TB*LDA, LDA, fc + 8*32, lane, d);
        store_d(d, s_K + ag*TB*LDA, LDA, bc1 + ag*128, wn*32, lane, K_LKYRND);  // h1
    }
    __syncthreads();

    // ---------------- P5a: critic layer 2 (tensor, 128 -> 16pad) partials ----------------
    {
        const int nt = wn & 1, kph = wn >> 1;
        const int ra = lane >> 2, ca = lane & 3;
        float d[4];
        #pragma unroll
        for (int i = 0; i < 4; i++) d[i] = 0.f;
        const float* Ab = s_K + ag*TB*LDA;
        const uint4* fc = g_fragv + F_WC2 + ag*512 + nt*256;
        #pragma unroll
        for (int kp2 = 0; kp2 < 4; kp2++) {
            const int kp = kph*4 + kp2;
            unsigned a[2][4];
            LOAD_AFRAG(a, Ab, LDA, kp);
            uint4 b = fc[kp*32 + lane];
            mma8(d, a[0], b.x, b.y);
            mma8(d, a[1], b.z, b.w);
        }
        // partials into s_in scratch: [ag][kph][row(16)][20]
        float* pp = s_in + (ag*2 + kph) * TB * 20;
        const int rr = lane >> 2, cc = (lane & 3)*2, col = nt*8 + cc;
        *(float2*)&pp[rr*20 + col]       = make_float2(d[0], d[1]);
        *(float2*)&pp[(rr + 8)*20 + col] = make_float2(d[2], d[3]);
        (void)ca; (void)ra;
    }
    __syncthreads();

    // ---------------- P5b: reduce partials + bias + store ----------------
    for (int idx = t; idx < TB * 27; idx += THREADS) {
        int e = idx / 27, rr = idx - e * 27;
        int nn = rr / 9,  a = rr - nn * 9;
        float v = s_in[(nn*2 + 0)*TB*20 + e*20 + a]
                + s_in[(nn*2 + 1)*TB*20 + e*20 + a]
                + bc2[nn*9 + a];
        out[(long)(e0g + e) * 27 + rr] = v;
    }
}

extern "C" void kernel_launch(void* const* d_in, const int* in_sizes, int n_in,
                              void* d_out, int out_size) {
    const float* obs  = (const float*)d_in[0];
    const float* act  = (const float*)d_in[1];
    const float* W_o  = (const float*)d_in[2];
    const float* b_o  = (const float*)d_in[3];
    const float* W_oa = (const float*)d_in[4];
    const float* b_oa = (const float*)d_in[5];
    const float* Wq   = (const float*)d_in[6];
    const float* bq   = (const float*)d_in[7];
    const float* Wk   = (const float*)d_in[8];
    const float* bk   = (const float*)d_in[9];
    const float* Wv   = (const float*)d_in[10];
    const float* bv   = (const float*)d_in[11];
    const float* Wc1  = (const float*)d_in[12];
    const float* bc1  = (const float*)d_in[13];
    const float* Wc2  = (const float*)d_in[14];
    const float* bc2  = (const float*)d_in[15];
    float* out = (float*)d_out;

    const int batch = in_sizes[0] / (3 * 30);   // 131072
    const int grid  = batch / TB;               // 8192
    const size_t smem = SMEM_FLOATS * sizeof(float);  // 108.75 KB

    prep_kernel<<<744, 256>>>(W_o, W_oa, Wq, Wk, Wv, Wc1, Wc2);

    cudaFuncSetAttribute(valuenet_kernel,
                         cudaFuncAttributeMaxDynamicSharedMemorySize, (int)smem);
    valuenet_kernel<<<grid, THREADS, smem>>>(
        obs, act, b_o, b_oa, bq, bk, bv, bc1, bc2, out);
}